// round 2
// baseline (speedup 1.0000x reference)
#include <cuda_runtime.h>

#define HH   640
#define WW   640
#define BATCH 4
#define NLAB 10
#define NPIX (HH*WW)

// Scratch (allocation-free rule: __device__ globals)
__device__ float d_F[BATCH*NPIX];      // |g_gen - max(g_vis, g_mean7)| per pixel (unmasked)
__device__ float d_E[BATCH*NPIX];      // |gen - max(vis, mean7)| per pixel
__device__ float d_accIn[BATCH];
__device__ float d_accGrad[BATCH];
__device__ float d_boxF[BATCH*NLAB];
__device__ float d_boxE[BATCH*NLAB];

__global__ void init_k() {
    int t = threadIdx.x;
    if (t < BATCH) { d_accIn[t] = 0.f; d_accGrad[t] = 0.f; }
    if (t < BATCH*NLAB) { d_boxF[t] = 0.f; d_boxE[t] = 0.f; }
}

__device__ __forceinline__ float wsum(float v) {
    #pragma unroll
    for (int o = 16; o; o >>= 1) v += __shfl_down_sync(0xffffffffu, v, o);
    return v;
}

// Global pass: smem-tiled sobel of vis, th, gen. Produces:
//  - per-batch sums of |gen - max(vis, 0.5v+0.5t)|  (loss_in)
//  - per-batch sums of |g_gen - max(g_vis, g_mean)| (loss_grad)
//  - per-pixel fields F, E used by the box pass.
__global__ __launch_bounds__(256) void global_pass(
    const float* __restrict__ vis, const float* __restrict__ th,
    const float* __restrict__ gen)
{
    __shared__ float sV[10][34];
    __shared__ float sT[10][34];
    __shared__ float sG[10][34];
    __shared__ float redIn[8], redGr[8];

    const int tx = threadIdx.x, ty = threadIdx.y;
    const int tid = ty * 32 + tx;
    const int base = blockIdx.z * NPIX;
    const int r0 = blockIdx.y * 8 - 1;
    const int c0 = blockIdx.x * 32 - 1;

    for (int i = tid; i < 340; i += 256) {
        int lr = i / 34, lc = i % 34;
        int gr = r0 + lr, gc = c0 + lc;
        bool in = (gr >= 0) & (gr < HH) & (gc >= 0) & (gc < WW);
        int q = in ? base + gr * WW + gc : base;
        float fv = in ? vis[q] : 0.f;
        float ft = in ? th[q]  : 0.f;
        float fg = in ? gen[q] : 0.f;
        sV[lr][lc] = fv; sT[lr][lc] = ft; sG[lr][lc] = fg;
    }
    __syncthreads();

    const int lr = ty + 1, lc = tx + 1;
    float gxV, gyV, gxT, gyT, gxG, gyG;
    {
        float a = sV[lr-1][lc-1], b = sV[lr-1][lc], c = sV[lr-1][lc+1];
        float d = sV[lr][lc-1],                     e = sV[lr][lc+1];
        float f = sV[lr+1][lc-1], g = sV[lr+1][lc], h = sV[lr+1][lc+1];
        gxV = (c - a) + 2.f*(e - d) + (h - f);
        gyV = (a - f) + 2.f*(b - g) + (c - h);
    }
    {
        float a = sT[lr-1][lc-1], b = sT[lr-1][lc], c = sT[lr-1][lc+1];
        float d = sT[lr][lc-1],                     e = sT[lr][lc+1];
        float f = sT[lr+1][lc-1], g = sT[lr+1][lc], h = sT[lr+1][lc+1];
        gxT = (c - a) + 2.f*(e - d) + (h - f);
        gyT = (a - f) + 2.f*(b - g) + (c - h);
    }
    {
        float a = sG[lr-1][lc-1], b = sG[lr-1][lc], c = sG[lr-1][lc+1];
        float d = sG[lr][lc-1],                     e = sG[lr][lc+1];
        float f = sG[lr+1][lc-1], g = sG[lr+1][lc], h = sG[lr+1][lc+1];
        gxG = (c - a) + 2.f*(e - d) + (h - f);
        gyG = (a - f) + 2.f*(b - g) + (c - h);
    }

    float v = sV[lr][lc], t = sT[lr][lc], g = sG[lr][lc];
    float gradV = fabsf(gxV) + fabsf(gyV);
    float grad5 = fabsf(0.5f*gxV + 0.5f*gxT) + fabsf(0.5f*gyV + 0.5f*gyT);
    float grad7 = fabsf(0.3f*gxV + 0.7f*gxT) + fabsf(0.3f*gyV + 0.7f*gyT);
    float gradG = fabsf(gxG) + fabsf(gyG);

    float li = fabsf(g - fmaxf(v, 0.5f*v + 0.5f*t));
    float lg = fabsf(gradG - fmaxf(gradV, grad5));

    int p = base + (r0 + lr) * WW + (c0 + lc);
    d_F[p] = fabsf(gradG - fmaxf(gradV, grad7));
    d_E[p] = fabsf(g - fmaxf(v, 0.3f*v + 0.7f*t));

    li = wsum(li); lg = wsum(lg);
    if ((tid & 31) == 0) { redIn[tid >> 5] = li; redGr[tid >> 5] = lg; }
    __syncthreads();
    if (tid == 0) {
        float a = 0.f, b = 0.f;
        #pragma unroll
        for (int i = 0; i < 8; i++) { a += redIn[i]; b += redGr[i]; }
        atomicAdd(&d_accIn[blockIdx.z],  a);
        atomicAdd(&d_accGrad[blockIdx.z], b);
    }
}

// Box pass: sum E everywhere in the box (pointwise-exact), sum F in the
// interior, and recompute masked sobel exactly only on the 1-px boundary ring.
__global__ __launch_bounds__(256) void box_pass(
    const float* __restrict__ vis, const float* __restrict__ th,
    const float* __restrict__ gen, const int* __restrict__ label)
{
    const int box = blockIdx.x;
    const int bi = box / NLAB;
    const int* L = label + box * 5;
    const int x1 = L[1], y1 = L[2], x2 = L[3], y2 = L[4];
    const int wdt = x2 - x1, hgt = y2 - y1;
    if (wdt <= 0 || hgt <= 0) return;
    const int area = wdt * hgt;
    const int base = bi * NPIX;

    float sF = 0.f, sE = 0.f;
    for (int idx = blockIdx.y * blockDim.x + threadIdx.x; idx < area;
         idx += gridDim.y * blockDim.x)
    {
        int r = y1 + idx / wdt;
        int c = x1 + idx % wdt;
        int p = base + r * WW + c;
        sE += d_E[p];
        if (r > y1 && r < y2 - 1 && c > x1 && c < x2 - 1) {
            sF += d_F[p];   // full 3x3 neighborhood inside box -> global sobel exact
        } else {
            // exact masked sobel on the ring
            float mv[9], mt[9], mg[9];
            #pragma unroll
            for (int dr = 0; dr < 3; dr++)
            #pragma unroll
            for (int dc = 0; dc < 3; dc++) {
                int rr = r + dr - 1, cc = c + dc - 1;
                bool in = (rr >= y1) & (rr < y2) & (cc >= x1) & (cc < x2);
                int q = in ? base + rr * WW + cc : base;
                mv[dr*3+dc] = in ? vis[q] : 0.f;
                mt[dr*3+dc] = in ? th[q]  : 0.f;
                mg[dr*3+dc] = in ? gen[q] : 0.f;
            }
            float gxV = (mv[2]-mv[0]) + 2.f*(mv[5]-mv[3]) + (mv[8]-mv[6]);
            float gyV = (mv[0]-mv[6]) + 2.f*(mv[1]-mv[7]) + (mv[2]-mv[8]);
            float gxT = (mt[2]-mt[0]) + 2.f*(mt[5]-mt[3]) + (mt[8]-mt[6]);
            float gyT = (mt[0]-mt[6]) + 2.f*(mt[1]-mt[7]) + (mt[2]-mt[8]);
            float gxG = (mg[2]-mg[0]) + 2.f*(mg[5]-mg[3]) + (mg[8]-mg[6]);
            float gyG = (mg[0]-mg[6]) + 2.f*(mg[1]-mg[7]) + (mg[2]-mg[8]);
            float gradV = fabsf(gxV) + fabsf(gyV);
            float grad7 = fabsf(0.3f*gxV + 0.7f*gxT) + fabsf(0.3f*gyV + 0.7f*gyT);
            float gradG = fabsf(gxG) + fabsf(gyG);
            sF += fabsf(gradG - fmaxf(gradV, grad7));
        }
    }

    sF = wsum(sF); sE = wsum(sE);
    if ((threadIdx.x & 31) == 0) {
        atomicAdd(&d_boxF[box], sF);
        atomicAdd(&d_boxE[box], sE);
    }
}

__global__ void finalize_k(const float* __restrict__ bptr,
                           const float* __restrict__ cptr,
                           const int* __restrict__ label,
                           float* __restrict__ out)
{
    __shared__ float Ls[BATCH*NLAB], L1[BATCH*NLAB];
    int t = threadIdx.x;
    if (t < BATCH*NLAB) {
        const int* L = label + t * 5;
        int x1 = L[1], y1 = L[2], x2 = L[3], y2 = L[4];
        bool valid = !(x1 == 0 && y1 == 0 && x2 == 0 && y2 == 0);
        float area = (float)((y2 - y1) * (x2 - x1));   // C == 1
        float sa = fmaxf(area, 1.0f);
        float v = valid ? 1.f : 0.f;
        Ls[t] = (d_boxF[t] / sa) * v;
        L1[t] = (d_boxE[t] / sa) * v;
    }
    __syncthreads();
    if (t < BATCH) {
        float sLs = 0.f, sL1 = 0.f, cnt = 0.f;
        for (int n = 0; n < NLAB; n++) {
            float a = Ls[t*NLAB + n], b = L1[t*NLAB + n];
            sLs += a; sL1 += b;
            if (a != 0.f || b != 0.f) cnt += 1.f;
        }
        float safe_cnt = fmaxf(cnt, 1.f);
        float ls  = (cnt > 0.f) ? sLs / safe_cnt : 0.f;
        float lin = (cnt > 0.f) ? sL1 / safe_cnt : 0.f;
        float alpha = *bptr, beta = *cptr;
        const float inv = 1.0f / (float)(HH * WW);     // C == 1
        float loss_in   = d_accIn[t]  * inv;
        float loss_grad = d_accGrad[t] * inv;
        out[0*BATCH + t] = 0.f;                                      // loss_ss
        out[1*BATCH + t] = alpha * loss_in + (1.f - alpha) * loss_grad; // loss_global
        out[2*BATCH + t] = (1.f - beta) * ls + beta * lin;           // loss_label
        out[3*BATCH + t] = loss_in;
        out[4*BATCH + t] = loss_grad;
        out[5*BATCH + t] = ls;
        out[6*BATCH + t] = lin;
    }
}

extern "C" void kernel_launch(void* const* d_in, const int* in_sizes, int n_in,
                              void* d_out, int out_size)
{
    (void)in_sizes; (void)n_in; (void)out_size;
    const float* bptr  = (const float*)d_in[0];
    const float* cptr  = (const float*)d_in[1];
    const float* vis   = (const float*)d_in[2];
    // d_in[3] = image_ir (unused by the reference)
    const float* gen   = (const float*)d_in[4];
    const int*   label = (const int*)d_in[5];
    const float* th    = (const float*)d_in[6];
    float* out = (float*)d_out;

    init_k<<<1, 64>>>();
    dim3 gb(WW / 32, HH / 8, BATCH);
    dim3 tb(32, 8);
    global_pass<<<gb, tb>>>(vis, th, gen);
    box_pass<<<dim3(BATCH*NLAB, 32), 256>>>(vis, th, gen, label);
    finalize_k<<<1, 64>>>(bptr, cptr, label, out);
}

// round 3
// speedup vs baseline: 1.3407x; 1.3407x over previous
#include <cuda_runtime.h>

#define HH    640
#define WW    640
#define BATCH 4
#define NLAB  10
#define NPIX  (HH*WW)
#define TILE_W 128
#define TILE_H 8
#define GXB (WW/TILE_W)            // 5
#define GYB (HH/TILE_H)            // 80
#define NBLOCKS (GXB*GYB*BATCH)    // 1600

// Persistent accumulators (zero-initialized at load; kernel restores zeros each call)
__device__ float d_accIn[BATCH];
__device__ float d_accGrad[BATCH];
__device__ float d_boxF[BATCH*NLAB];
__device__ float d_boxE[BATCH*NLAB];
__device__ unsigned d_count;

__device__ __forceinline__ float wsum(float v) {
    #pragma unroll
    for (int o = 16; o; o >>= 1) v += __shfl_down_sync(0xffffffffu, v, o);
    return v;
}

struct G4 { float gx[4], gy[4], c[4]; };

// Separable sobel for a 1x4 output strip from a shared tile.
__device__ __forceinline__ G4 sobel4(const float sm[10][132], int ty, int lc0) {
    G4 o;
    float t1[3][4], t2[3][4];
    #pragma unroll
    for (int r = 0; r < 3; r++) {
        const float* row = &sm[ty + r][lc0];
        float4 a = *reinterpret_cast<const float4*>(row);
        float2 b = *reinterpret_cast<const float2*>(row + 4);
        float v0=a.x, v1=a.y, v2=a.z, v3=a.w, v4=b.x, v5=b.y;
        t1[r][0]=v0+2.f*v1+v2; t1[r][1]=v1+2.f*v2+v3;
        t1[r][2]=v2+2.f*v3+v4; t1[r][3]=v3+2.f*v4+v5;
        t2[r][0]=v2-v0; t2[r][1]=v3-v1; t2[r][2]=v4-v2; t2[r][3]=v5-v3;
        if (r == 1) { o.c[0]=v1; o.c[1]=v2; o.c[2]=v3; o.c[3]=v4; }
    }
    #pragma unroll
    for (int k = 0; k < 4; k++) {
        o.gx[k] = t2[0][k] + 2.f*t2[1][k] + t2[2][k];
        o.gy[k] = t1[0][k] - t1[2][k];
    }
    return o;
}

// Exact masked sobel F at a ring pixel, using the shared tiles (halo covers ±1).
__device__ float maskedF(const float sV[10][132], const float sT[10][132],
                         const float sG[10][132], int ty, int lcc,
                         int r, int c, int4 B)
{
    const float wx[3][3] = {{-1,0,1},{-2,0,2},{-1,0,1}};
    const float wy[3][3] = {{1,2,1},{0,0,0},{-1,-2,-1}};
    float gxV=0,gyV=0,gxT=0,gyT=0,gxG=0,gyG=0;
    #pragma unroll
    for (int dr = 0; dr < 3; dr++)
    #pragma unroll
    for (int dc = 0; dc < 3; dc++) {
        int rr = r + dr - 1, cc = c + dc - 1;
        bool in = (rr >= B.y) & (rr < B.w) & (cc >= B.x) & (cc < B.z);
        float m = in ? 1.f : 0.f;
        float fv = sV[ty + dr][lcc - 1 + dc] * m;
        float ft = sT[ty + dr][lcc - 1 + dc] * m;
        float fg = sG[ty + dr][lcc - 1 + dc] * m;
        gxV += wx[dr][dc] * fv; gyV += wy[dr][dc] * fv;
        gxT += wx[dr][dc] * ft; gyT += wy[dr][dc] * ft;
        gxG += wx[dr][dc] * fg; gyG += wy[dr][dc] * fg;
    }
    float gradV = fabsf(gxV) + fabsf(gyV);
    float grad7 = fabsf(0.3f*gxV + 0.7f*gxT) + fabsf(0.3f*gyV + 0.7f*gyT);
    float gradG = fabsf(gxG) + fabsf(gyG);
    return fabsf(gradG - fmaxf(gradV, grad7));
}

__global__ __launch_bounds__(256) void fused_k(
    const float* __restrict__ vis, const float* __restrict__ th,
    const float* __restrict__ gen, const int* __restrict__ label,
    const float* __restrict__ bptr, const float* __restrict__ cptr,
    float* __restrict__ out)
{
    __shared__ float sV[10][132], sT[10][132], sG[10][132];
    __shared__ int4  sBox[NLAB];
    __shared__ int   sBoxIdx[NLAB];
    __shared__ float sAF[NLAB], sAE[NLAB];
    __shared__ int   sN;
    __shared__ float sRedI[8], sRedG[8];
    __shared__ int   sIsLast;
    __shared__ float sLs[BATCH*NLAB], sL1[BATCH*NLAB];

    const int tx = threadIdx.x, ty = threadIdx.y;
    const int tid = ty * 32 + tx;
    const int bz = blockIdx.z;
    const int colStart = blockIdx.x * TILE_W;
    const int rowStart = blockIdx.y * TILE_H;
    const int base = bz * NPIX;

    if (tid == 0) sN = 0;
    if (tid < NLAB) { sAF[tid] = 0.f; sAE[tid] = 0.f; }

    // Load 10x130 halo tiles of the 3 images
    for (int i = tid; i < 10 * 130; i += 256) {
        int lr = i / 130, lc = i - lr * 130;
        int gr = rowStart - 1 + lr, gc = colStart - 1 + lc;
        bool in = (gr >= 0) & (gr < HH) & (gc >= 0) & (gc < WW);
        int q = in ? base + gr * WW + gc : base;
        float fv = in ? vis[q] : 0.f;
        float ft = in ? th[q]  : 0.f;
        float fg = in ? gen[q] : 0.f;
        sV[lr][lc] = fv; sT[lr][lc] = ft; sG[lr][lc] = fg;
    }
    __syncthreads();

    // Build overlapping-box list for this tile (only boxes of this batch image)
    if (tid < NLAB) {
        const int* L = label + (bz * NLAB + tid) * 5;
        int x1 = L[1], y1 = L[2], x2 = L[3], y2 = L[4];
        if (x2 > x1 && y2 > y1 &&
            x1 < colStart + TILE_W && x2 > colStart &&
            y1 < rowStart + TILE_H && y2 > rowStart) {
            int p = atomicAdd(&sN, 1);
            sBox[p] = make_int4(x1, y1, x2, y2);
            sBoxIdx[p] = bz * NLAB + tid;
        }
    }
    __syncthreads();

    // Stencils
    const int lc0 = tx * 4;
    G4 gv = sobel4(sV, ty, lc0);
    G4 gt = sobel4(sT, ty, lc0);
    G4 gg = sobel4(sG, ty, lc0);

    float F[4], E[4];
    float li = 0.f, lg = 0.f;
    #pragma unroll
    for (int k = 0; k < 4; k++) {
        float gradV = fabsf(gv.gx[k]) + fabsf(gv.gy[k]);
        float gradG = fabsf(gg.gx[k]) + fabsf(gg.gy[k]);
        float g5 = fabsf(0.5f*(gv.gx[k] + gt.gx[k])) + fabsf(0.5f*(gv.gy[k] + gt.gy[k]));
        float g7 = fabsf(0.3f*gv.gx[k] + 0.7f*gt.gx[k]) + fabsf(0.3f*gv.gy[k] + 0.7f*gt.gy[k]);
        float xm  = 0.5f * (gv.c[k] + gt.c[k]);
        float xm7 = 0.3f * gv.c[k] + 0.7f * gt.c[k];
        li  += fabsf(gg.c[k] - fmaxf(gv.c[k], xm));
        lg  += fabsf(gradG - fmaxf(gradV, g5));
        F[k] = fabsf(gradG - fmaxf(gradV, g7));
        E[k] = fabsf(gg.c[k] - fmaxf(gv.c[k], xm7));
    }

    // Per-box accumulation: interior reuses F, ring pixels recompute masked sobel
    const int r = rowStart + ty;
    const int cbase = colStart + tx * 4;
    const int nOv = sN;
    for (int b = 0; b < nOv; b++) {
        int4 B = sBox[b];
        float fb = 0.f, eb = 0.f;
        bool rowIn = (r >= B.y) & (r < B.w);
        if (rowIn) {
            bool rowInt = (r > B.y) & (r < B.w - 1);
            #pragma unroll
            for (int k = 0; k < 4; k++) {
                int c = cbase + k;
                if (c >= B.x && c < B.z) {
                    eb += E[k];
                    if (rowInt && c > B.x && c < B.z - 1) fb += F[k];
                    else fb += maskedF(sV, sT, sG, ty, lc0 + k + 1, r, c, B);
                }
            }
        }
        fb = wsum(fb); eb = wsum(eb);
        if ((tid & 31) == 0) { atomicAdd(&sAF[b], fb); atomicAdd(&sAE[b], eb); }
    }

    // Block reduce li/lg
    li = wsum(li); lg = wsum(lg);
    if ((tid & 31) == 0) { sRedI[tid >> 5] = li; sRedG[tid >> 5] = lg; }
    __syncthreads();
    if (tid == 0) {
        float a = 0.f, bb = 0.f;
        #pragma unroll
        for (int i = 0; i < 8; i++) { a += sRedI[i]; bb += sRedG[i]; }
        atomicAdd(&d_accIn[bz], a);
        atomicAdd(&d_accGrad[bz], bb);
    }
    if (tid < nOv) {
        atomicAdd(&d_boxF[sBoxIdx[tid]], sAF[tid]);
        atomicAdd(&d_boxE[sBoxIdx[tid]], sAE[tid]);
    }

    // Last-block finalize
    __threadfence();
    __syncthreads();
    if (tid == 0) {
        unsigned o = atomicAdd(&d_count, 1u);
        sIsLast = (o == NBLOCKS - 1);
    }
    __syncthreads();
    if (!sIsLast) return;

    if (tid < BATCH * NLAB) {
        const int* L = label + tid * 5;
        int x1 = L[1], y1 = L[2], x2 = L[3], y2 = L[4];
        bool valid = !(x1 == 0 && y1 == 0 && x2 == 0 && y2 == 0);
        float area = (float)((y2 - y1) * (x2 - x1));       // C == 1
        float sa = fmaxf(area, 1.f);
        volatile float* vF = (volatile float*)d_boxF;
        volatile float* vE = (volatile float*)d_boxE;
        float f = vF[tid], e = vE[tid];
        float vv = valid ? 1.f : 0.f;
        sLs[tid] = (f / sa) * vv;
        sL1[tid] = (e / sa) * vv;
        d_boxF[tid] = 0.f; d_boxE[tid] = 0.f;              // reset for next call
    }
    __syncthreads();
    if (tid < BATCH) {
        volatile float* aI = (volatile float*)d_accIn;
        volatile float* aG = (volatile float*)d_accGrad;
        const float inv = 1.0f / (float)NPIX;              // C == 1
        float loss_in   = aI[tid] * inv;
        float loss_grad = aG[tid] * inv;
        d_accIn[tid] = 0.f; d_accGrad[tid] = 0.f;          // reset

        float sLsum = 0.f, s1sum = 0.f, cnt = 0.f;
        for (int n = 0; n < NLAB; n++) {
            float a = sLs[tid * NLAB + n], bb = sL1[tid * NLAB + n];
            sLsum += a; s1sum += bb;
            if (a != 0.f || bb != 0.f) cnt += 1.f;
        }
        float safe_cnt = fmaxf(cnt, 1.f);
        float ls  = (cnt > 0.f) ? sLsum / safe_cnt : 0.f;
        float lin = (cnt > 0.f) ? s1sum / safe_cnt : 0.f;
        float alpha = *bptr, beta = *cptr;
        out[0*BATCH + tid] = 0.f;                                         // loss_ss
        out[1*BATCH + tid] = alpha * loss_in + (1.f - alpha) * loss_grad; // loss_global
        out[2*BATCH + tid] = (1.f - beta) * ls + beta * lin;              // loss_label
        out[3*BATCH + tid] = loss_in;
        out[4*BATCH + tid] = loss_grad;
        out[5*BATCH + tid] = ls;
        out[6*BATCH + tid] = lin;
    }
    if (tid == 0) d_count = 0;                                            // reset
}

extern "C" void kernel_launch(void* const* d_in, const int* in_sizes, int n_in,
                              void* d_out, int out_size)
{
    (void)in_sizes; (void)n_in; (void)out_size;
    const float* bptr  = (const float*)d_in[0];
    const float* cptr  = (const float*)d_in[1];
    const float* vis   = (const float*)d_in[2];
    // d_in[3] = image_ir (unused by the reference)
    const float* gen   = (const float*)d_in[4];
    const int*   label = (const int*)d_in[5];
    const float* th    = (const float*)d_in[6];
    float* out = (float*)d_out;

    dim3 grid(GXB, GYB, BATCH);
    dim3 blk(32, 8);
    fused_k<<<grid, blk>>>(vis, th, gen, label, bptr, cptr, out);
}